// round 16
// baseline (speedup 1.0000x reference)
#include <cuda_runtime.h>
#include <cuda_fp16.h>
#include <math.h>
#include <cstdint>

// Shapes: x[32,512,2048] f32, w_qkv[6144,2048], w_out[2048,2048], out[32,512,2048]

// Scratch (device globals: allocation-free per harness rules)
__device__ __half g_qh[32L * 16 * 512 * 128];   // [B,H,T,D] fp16, roped+scaled at gemm epilogue
__device__ __half g_kh[32L * 16 * 512 * 128];   // roped at gemm epilogue
__device__ __half g_vh[32L * 16 * 512 * 128];
__device__ __half g_yh[32L * 512 * 2048];       // [B,T,C] attn out fp16
__device__ __half g_xh[32L * 512 * 2048];       // x fp16
__device__ __half g_wqh[6144L * 2048];          // w_qkv fp16
__device__ __half g_woh[2048L * 2048];          // w_out fp16
__device__ float  g_cos[512 * 32];
__device__ float  g_sin[512 * 32];

// ===========================================================================
// Helpers
// ===========================================================================
__device__ __forceinline__ uint32_t smem_u32(const void* p) {
    uint32_t a;
    asm("{ .reg .u64 t; cvta.to.shared.u64 t, %1; cvt.u32.u64 %0, t; }" : "=r"(a) : "l"(p));
    return a;
}
__device__ __forceinline__ uint32_t swz(uint32_t off) { return off ^ ((off >> 3) & 0x70); }

#define CP_ASYNC16(dst, src) \
    asm volatile("cp.async.cg.shared.global [%0], [%1], 16;" :: "r"(dst), "l"(src))
#define CP_COMMIT() asm volatile("cp.async.commit_group;" ::: "memory")
#define CP_WAIT1() asm volatile("cp.async.wait_group 1;" ::: "memory")
#define CP_WAIT0() asm volatile("cp.async.wait_group 0;" ::: "memory")

#define MMA_F16(c, A0, A1, A2, A3, B0, B1) \
    asm volatile("mma.sync.aligned.m16n8k16.row.col.f32.f16.f16.f32 " \
        "{%0,%1,%2,%3},{%4,%5,%6,%7},{%8,%9},{%0,%1,%2,%3};" \
        : "+f"((c)[0]), "+f"((c)[1]), "+f"((c)[2]), "+f"((c)[3]) \
        : "r"(A0), "r"(A1), "r"(A2), "r"(A3), "r"(B0), "r"(B1))

#define LDMX4(r, addr) \
    asm volatile("ldmatrix.sync.aligned.m8n8.x4.shared.b16 {%0,%1,%2,%3}, [%4];" \
        : "=r"((r)[0]), "=r"((r)[1]), "=r"((r)[2]), "=r"((r)[3]) : "r"(addr))
#define LDMX4T(r, addr) \
    asm volatile("ldmatrix.sync.aligned.m8n8.x4.trans.shared.b16 {%0,%1,%2,%3}, [%4];" \
        : "=r"((r)[0]), "=r"((r)[1]), "=r"((r)[2]), "=r"((r)[3]) : "r"(addr))

__device__ __forceinline__ uint32_t pack2(float a, float b) {
    const __half2 h = __floats2half2_rn(a, b);
    return *(const uint32_t*)&h;
}

// ===========================================================================
// Merged prep: f32->f16 of x, w_qkv, w_out + rope tables. One launch.
// ===========================================================================
#define N4_X  8388608
#define N4_WQ 3145728
#define N4_WO 1048576
#define N4_TOTAL (N4_X + N4_WQ + N4_WO)

__global__ void prep_all(const float* __restrict__ x,
                         const float* __restrict__ wq,
                         const float* __restrict__ wo)
{
    const int i = blockIdx.x * blockDim.x + threadIdx.x;
    if (i < 512 * 32) {
        const int t = i >> 5, j = i & 31;
        const double freq = pow(10000.0, -(double)j / 32.0);
        const double ang = (double)t * freq;
        g_cos[i] = (float)cos(ang);
        g_sin[i] = (float)sin(ang);
    }
    if (i >= N4_TOTAL) return;
    const float* in;
    __half* out;
    int idx = i;
    if (idx < N4_X) { in = x; out = g_xh; }
    else if (idx < N4_X + N4_WQ) { idx -= N4_X; in = wq; out = g_wqh; }
    else { idx -= N4_X + N4_WQ; in = wo; out = g_woh; }
    const float4 v = ((const float4*)in)[idx];
    ((__half2*)out)[idx * 2]     = __floats2half2_rn(v.x, v.y);
    ((__half2*)out)[idx * 2 + 1] = __floats2half2_rn(v.z, v.w);
}

// ===========================================================================
// fp16 mma.sync GEMM: 128x128 CTA tile, BK=64, 4 warps (2x2) x 64x64 warp
// tile, 128 threads, 2 CTA/SM.
// 3-stage cp.async pipeline, ONE __syncthreads per chunk, prefetch issue
// interleaved into the 4 ks compute steps (no LDGSTS burst after the bar).
// MODE 0: fp32 row-major store.
// MODE 1: scatter q/k/v fp16 [B,H,T,D] with FUSED ROPE (+1/sqrt(D) q-scale).
// ===========================================================================
#define GEMM_SMEM_BYTES 98304   // 3 stages x (16KB A + 16KB B)

template <int MODE>
__global__ void __launch_bounds__(128, 2) gemm_h(
    const __half* __restrict__ A, const __half* __restrict__ Bm,
    float* __restrict__ Cout, int M, int N, int K)
{
    extern __shared__ char smraw[];
    const uint32_t sb = smem_u32(smraw);
    const int tid = threadIdx.x;
    const int warp = tid >> 5, lane = tid & 31;
    const int wm = warp >> 1, wn = warp & 1;
    const int m0 = blockIdx.y * 128, n0 = blockIdx.x * 128;
    const int lrow = lane & 15, lcol = (lane >> 4) * 16;

    float acc[4][8][4];
#pragma unroll
    for (int i = 0; i < 4; i++)
#pragma unroll
        for (int j = 0; j < 8; j++)
#pragma unroll
            for (int q = 0; q < 4; q++) acc[i][j][q] = 0.f;

    const int nch = K / 64;   // 32

    // full-chunk load (prologue only): 8 A iters + 8 B iters, 16 LDGSTS/thread
    auto load_chunk = [&](int c, int buf) {
        const int k0 = c * 64;
        const uint32_t abase = sb + buf * 32768;
        const uint32_t bbase = abase + 16384;
#pragma unroll
        for (int it = 0; it < 8; it++) {
            const int t = tid + it * 128;
            const int row = t >> 3, ch = t & 7;
            CP_ASYNC16(abase + swz((uint32_t)(row * 128 + ch * 16)),
                       A + (size_t)(m0 + row) * K + k0 + ch * 8);
        }
#pragma unroll
        for (int it = 0; it < 8; it++) {
            const int t = tid + it * 128;
            const int row = t >> 3, ch = t & 7;
            CP_ASYNC16(bbase + swz((uint32_t)(row * 128 + ch * 16)),
                       Bm + (size_t)(n0 + row) * K + k0 + ch * 8);
        }
    };
    // quarter load: iters {2q, 2q+1} of A and B = 4 LDGSTS/thread
    auto load_quarter = [&](int k0, int buf, int q) {
        const uint32_t abase = sb + buf * 32768;
        const uint32_t bbase = abase + 16384;
#pragma unroll
        for (int it = 2 * q; it < 2 * q + 2; it++) {
            const int t = tid + it * 128;
            const int row = t >> 3, ch = t & 7;
            CP_ASYNC16(abase + swz((uint32_t)(row * 128 + ch * 16)),
                       A + (size_t)(m0 + row) * K + k0 + ch * 8);
            CP_ASYNC16(bbase + swz((uint32_t)(row * 128 + ch * 16)),
                       Bm + (size_t)(n0 + row) * K + k0 + ch * 8);
        }
    };

    load_chunk(0, 0); CP_COMMIT();
    load_chunk(1, 1); CP_COMMIT();

    for (int c = 0; c < nch; c++) {
        // wait for chunk c (groups outstanding: c, c+1)
        if (c + 1 < nch) { CP_WAIT1(); } else { CP_WAIT0(); }
        __syncthreads();   // also: buffer (c+2)%3's last readers were iter c-1

        const bool pf = (c + 2 < nch);
        const int pbuf = (c + 2) % 3;
        const int pk0 = (c + 2) * 64;

        const uint32_t abase = sb + (c % 3) * 32768;
        const uint32_t bbase = abase + 16384;

#pragma unroll
        for (int ks = 0; ks < 4; ks++) {
            if (pf) load_quarter(pk0, pbuf, ks);   // interleaved prefetch issue
            uint32_t a[4][4], b[4][4];
#pragma unroll
            for (int mf = 0; mf < 4; mf++) {
                const int row = wm * 64 + mf * 16 + lrow;
                LDMX4(a[mf], abase + swz((uint32_t)(row * 128 + ks * 32 + lcol)));
            }
#pragma unroll
            for (int nb = 0; nb < 4; nb++) {
                const int row = wn * 64 + nb * 16 + lrow;
                LDMX4(b[nb], bbase + swz((uint32_t)(row * 128 + ks * 32 + lcol)));
            }
#pragma unroll
            for (int mf = 0; mf < 4; mf++)
#pragma unroll
                for (int nf = 0; nf < 8; nf++) {
                    const int nb = nf >> 1, i = nf & 1;
                    MMA_F16(acc[mf][nf], a[mf][0], a[mf][1], a[mf][2], a[mf][3],
                            b[nb][i], b[nb][i + 2]);
                }
        }
        if (pf) CP_COMMIT();
    }

    const int g = lane >> 2, tig = lane & 3;
    if (MODE == 0) {
#pragma unroll
        for (int mf = 0; mf < 4; mf++) {
            const int mA = m0 + wm * 64 + mf * 16 + g;
#pragma unroll
            for (int nf = 0; nf < 8; nf++) {
                const int nn = n0 + wn * 64 + nf * 8 + tig * 2;
                *(float2*)(Cout + (size_t)mA * N + nn) =
                    make_float2(acc[mf][nf][0], acc[mf][nf][1]);
                *(float2*)(Cout + (size_t)(mA + 8) * N + nn) =
                    make_float2(acc[mf][nf][2], acc[mf][nf][3]);
            }
        }
    } else {
        const int which = n0 >> 11;      // 0=q, 1=k, 2=v (uniform per CTA)
        const int h = (n0 & 2047) >> 7;
        __half* basep = (which == 0) ? g_qh : (which == 1) ? g_kh : g_vh;
        const float scale = (which == 0) ? 0.08838834764831845f : 1.0f;

        if (which <= 1 && wn == 0) {
            // rope dims d = 0..63: rotate pairs (nf, nf+4) = (j, j+32), then scale
#pragma unroll
            for (int mf = 0; mf < 4; mf++) {
                const int mA = m0 + wm * 64 + mf * 16 + g;
                const int bA = mA >> 9, tA = mA & 511;
                const int mB = mA + 8;
                const int bB = mB >> 9, tB = mB & 511;
#pragma unroll
                for (int nf = 0; nf < 4; nf++) {
                    const int j0 = nf * 8 + tig * 2;
                    const float cA0 = g_cos[tA * 32 + j0], sA0 = g_sin[tA * 32 + j0];
                    const float cA1 = g_cos[tA * 32 + j0 + 1], sA1 = g_sin[tA * 32 + j0 + 1];
                    const float cB0 = g_cos[tB * 32 + j0], sB0 = g_sin[tB * 32 + j0];
                    const float cB1 = g_cos[tB * 32 + j0 + 1], sB1 = g_sin[tB * 32 + j0 + 1];
                    const float x1A0 = acc[mf][nf][0], x2A0 = acc[mf][nf + 4][0];
                    const float x1A1 = acc[mf][nf][1], x2A1 = acc[mf][nf + 4][1];
                    const float x1B0 = acc[mf][nf][2], x2B0 = acc[mf][nf + 4][2];
                    const float x1B1 = acc[mf][nf][3], x2B1 = acc[mf][nf + 4][3];
                    const size_t iA = ((size_t)(bA * 16 + h) * 512 + tA) * 128 + j0;
                    const size_t iB = ((size_t)(bB * 16 + h) * 512 + tB) * 128 + j0;
                    *(__half2*)&basep[iA] = __floats2half2_rn(
                        (x1A0 * cA0 - x2A0 * sA0) * scale, (x1A1 * cA1 - x2A1 * sA1) * scale);
                    *(__half2*)&basep[iA + 32] = __floats2half2_rn(
                        (x2A0 * cA0 + x1A0 * sA0) * scale, (x2A1 * cA1 + x1A1 * sA1) * scale);
                    *(__half2*)&basep[iB] = __floats2half2_rn(
                        (x1B0 * cB0 - x2B0 * sB0) * scale, (x1B1 * cB1 - x2B1 * sB1) * scale);
                    *(__half2*)&basep[iB + 32] = __floats2half2_rn(
                        (x2B0 * cB0 + x1B0 * sB0) * scale, (x2B1 * cB1 + x1B1 * sB1) * scale);
                }
            }
        } else {
#pragma unroll
            for (int mf = 0; mf < 4; mf++) {
                const int mA = m0 + wm * 64 + mf * 16 + g;
                const int bA = mA >> 9, tA = mA & 511;
                const int mB = mA + 8;
                const int bB = mB >> 9, tB = mB & 511;
#pragma unroll
                for (int nf = 0; nf < 8; nf++) {
                    const int d = wn * 64 + nf * 8 + tig * 2;
                    const size_t iA = ((size_t)(bA * 16 + h) * 512 + tA) * 128 + d;
                    const size_t iB = ((size_t)(bB * 16 + h) * 512 + tB) * 128 + d;
                    *(__half2*)&basep[iA] = __floats2half2_rn(
                        acc[mf][nf][0] * scale, acc[mf][nf][1] * scale);
                    *(__half2*)&basep[iB] = __floats2half2_rn(
                        acc[mf][nf][2] * scale, acc[mf][nf][3] * scale);
                }
            }
        }
    }
}

// ===========================================================================
// Register-resident fp16 flash attention (R14, best known).
// Tq=64, 4 warps (16 q-rows each), full 64 keys x 128 d per warp.
// P in registers; warp-local softmax. Double-buffered K/V. 2 CTA/SM.
// ===========================================================================
#define ASQ   0                        // 64 x 272B
#define ASK(b) (17408 + (b) * 17408)   // 2 x 64x272B
#define ASV(b) (52224 + (b) * 17408)   // 2 x 64x272B
#define ATTN2_SMEM_BYTES 87040

__global__ void __launch_bounds__(128, 2) attn_mma()
{
    extern __shared__ char smc[];
    const uint32_t sb = smem_u32(smc);
    const int tid = threadIdx.x;
    const int warp = tid >> 5, lane = tid & 31;
    const int g = lane >> 2, tig = lane & 3;
    const int lrow = lane & 15, lcol = (lane >> 4) * 16;
    const int qt = blockIdx.x, hh = blockIdx.y, bb = blockIdx.z;
    const int bh = bb * 16 + hh, q0 = qt * 64;
    const int arow = warp * 16;

    const __half* qbase = g_qh + (size_t)bh * 512 * 128;
    const __half* kbase = g_kh + (size_t)bh * 512 * 128;
    const __half* vbase = g_vh + (size_t)bh * 512 * 128;

    auto stage = [&](uint32_t dstB, const __half* src) {
#pragma unroll
        for (int it = 0; it < 8; it++) {
            const int p = tid + it * 128;
            const int row = p >> 4, ch = p & 15;
            CP_ASYNC16(sb + dstB + row * 272 + ch * 16,
                       src + row * 128 + ch * 8);
        }
    };

    const int nkt = qt + 1;
    stage(ASQ, qbase + (size_t)q0 * 128);
    stage(ASK(0), kbase);
    stage(ASV(0), vbase);
    CP_COMMIT();
    if (nkt > 1) {
        stage(ASK(1), kbase + 64 * 128);
        stage(ASV(1), vbase + 64 * 128);
        CP_COMMIT();
    }

    float o[16][4];
#pragma unroll
    for (int i = 0; i < 16; i++)
#pragma unroll
        for (int q = 0; q < 4; q++) o[i][q] = 0.f;
    float mA = -1e30f, mB = -1e30f, lA = 0.f, lB = 0.f;

    for (int kt = 0; kt < nkt; kt++) {
        const int buf = kt & 1;
        if (kt < nkt - 1) { CP_WAIT1(); } else { CP_WAIT0(); }
        __syncthreads();

        float sacc[8][4];
#pragma unroll
        for (int nf = 0; nf < 8; nf++)
#pragma unroll
            for (int q = 0; q < 4; q++) sacc[nf][q] = 0.f;

#pragma unroll
        for (int dc = 0; dc < 8; dc++) {
            uint32_t a[4];
            LDMX4(a, sb + ASQ + (uint32_t)((arow + lrow) * 272 + dc * 32 + lcol));
#pragma unroll
            for (int nb = 0; nb < 4; nb++) {
                uint32_t bf[4];
                LDMX4(bf, sb + ASK(buf) +
                      (uint32_t)((nb * 16 + lrow) * 272 + dc * 32 + lcol));
#pragma unroll
                for (int i = 0; i < 2; i++)
                    MMA_F16(sacc[nb * 2 + i], a[0], a[1], a[2], a[3],
                            bf[i], bf[i + 2]);
            }
        }

        if (kt == qt) {
            const int lrA = arow + g, lrB = lrA + 8;
#pragma unroll
            for (int nf = 0; nf < 8; nf++) {
                const int lc = nf * 8 + 2 * tig;
                if (lc > lrA)     sacc[nf][0] = -1e30f;
                if (lc + 1 > lrA) sacc[nf][1] = -1e30f;
                if (lc > lrB)     sacc[nf][2] = -1e30f;
                if (lc + 1 > lrB) sacc[nf][3] = -1e30f;
            }
        }

        float mAn = -1e30f, mBn = -1e30f;
#pragma unroll
        for (int nf = 0; nf < 8; nf++) {
            mAn = fmaxf(mAn, fmaxf(sacc[nf][0], sacc[nf][1]));
            mBn = fmaxf(mBn, fmaxf(sacc[nf][2], sacc[nf][3]));
        }
        mAn = fmaxf(mAn, __shfl_xor_sync(0xffffffffu, mAn, 1));
        mAn = fmaxf(mAn, __shfl_xor_sync(0xffffffffu, mAn, 2));
        mBn = fmaxf(mBn, __shfl_xor_sync(0xffffffffu, mBn, 1));
        mBn = fmaxf(mBn, __shfl_xor_sync(0xffffffffu, mBn, 2));
        const float mAnew = fmaxf(mA, mAn), mBnew = fmaxf(mB, mBn);
        const float alA = __expf(mA - mAnew), alB = __expf(mB - mBnew);
        mA = mAnew; mB = mBnew;

        uint32_t pf[4][4];
        float sA = 0.f, sB = 0.f;
#pragma unroll
        for (int kc = 0; kc < 4; kc++) {
            const float p0 = __expf(sacc[2 * kc][0] - mA);
            const float p1 = __expf(sacc[2 * kc][1] - mA);
            const float p2 = __expf(sacc[2 * kc][2] - mB);
            const float p3 = __expf(sacc[2 * kc][3] - mB);
            const float p4 = __expf(sacc[2 * kc + 1][0] - mA);
            const float p5 = __expf(sacc[2 * kc + 1][1] - mA);
            const float p6 = __expf(sacc[2 * kc + 1][2] - mB);
            const float p7 = __expf(sacc[2 * kc + 1][3] - mB);
            sA += p0 + p1 + p4 + p5;
            sB += p2 + p3 + p6 + p7;
            pf[kc][0] = pack2(p0, p1);
            pf[kc][1] = pack2(p2, p3);
            pf[kc][2] = pack2(p4, p5);
            pf[kc][3] = pack2(p6, p7);
        }
        sA += __shfl_xor_sync(0xffffffffu, sA, 1);
        sA += __shfl_xor_sync(0xffffffffu, sA, 2);
        sB += __shfl_xor_sync(0xffffffffu, sB, 1);
        sB += __shfl_xor_sync(0xffffffffu, sB, 2);
        lA = lA * alA + sA;
        lB = lB * alB + sB;

#pragma unroll
        for (int i = 0; i < 16; i++) {
            o[i][0] *= alA; o[i][1] *= alA;
            o[i][2] *= alB; o[i][3] *= alB;
        }

#pragma unroll
        for (int kc = 0; kc < 4; kc++) {
#pragma unroll
            for (int dblk = 0; dblk < 8; dblk++) {
                uint32_t bf[4];
                LDMX4T(bf, sb + ASV(buf) +
                       (uint32_t)((kc * 16 + lrow) * 272 + dblk * 32 + lcol));
                MMA_F16(o[dblk * 2],     pf[kc][0], pf[kc][1], pf[kc][2], pf[kc][3],
                        bf[0], bf[1]);
                MMA_F16(o[dblk * 2 + 1], pf[kc][0], pf[kc][1], pf[kc][2], pf[kc][3],
                        bf[2], bf[3]);
            }
        }
        __syncthreads();

        if (kt + 2 < nkt) {
            const int knext = (kt + 2) * 64;
            stage(ASK(buf), kbase + (size_t)knext * 128);
            stage(ASV(buf), vbase + (size_t)knext * 128);
            CP_COMMIT();
        }
    }

    const float invA = 1.f / lA, invB = 1.f / lB;
    const int tA = q0 + arow + g, tB = tA + 8;
#pragma unroll
    for (int nf2 = 0; nf2 < 16; nf2++) {
        const int d = nf2 * 8 + 2 * tig;
        *(__half2*)&g_yh[((size_t)bb * 512 + tA) * 2048 + hh * 128 + d] =
            __floats2half2_rn(o[nf2][0] * invA, o[nf2][1] * invA);
        *(__half2*)&g_yh[((size_t)bb * 512 + tB) * 2048 + hh * 128 + d] =
            __floats2half2_rn(o[nf2][2] * invB, o[nf2][3] * invB);
    }
}

// ---------------------------------------------------------------------------
extern "C" void kernel_launch(void* const* d_in, const int* in_sizes, int n_in,
                              void* d_out, int out_size)
{
    (void)in_sizes; (void)n_in; (void)out_size;
    const float* x     = (const float*)d_in[0];
    const float* w_qkv = (const float*)d_in[1];
    const float* w_out = (const float*)d_in[2];
    float* out = (float*)d_out;

    __half *xh_ptr, *wqh_ptr, *woh_ptr, *yh_ptr;
    cudaGetSymbolAddress((void**)&xh_ptr,  g_xh);
    cudaGetSymbolAddress((void**)&wqh_ptr, g_wqh);
    cudaGetSymbolAddress((void**)&woh_ptr, g_woh);
    cudaGetSymbolAddress((void**)&yh_ptr,  g_yh);

    cudaFuncSetAttribute(gemm_h<1>, cudaFuncAttributeMaxDynamicSharedMemorySize, GEMM_SMEM_BYTES);
    cudaFuncSetAttribute(gemm_h<0>, cudaFuncAttributeMaxDynamicSharedMemorySize, GEMM_SMEM_BYTES);
    cudaFuncSetAttribute(attn_mma, cudaFuncAttributeMaxDynamicSharedMemorySize, ATTN2_SMEM_BYTES);

    // 0) merged prep (fp16 converts + rope tables)
    prep_all<<<(N4_TOTAL + 255) / 256, 256>>>(x, w_qkv, w_out);

    // 1) QKV projection with fused rope (+q scale) in epilogue
    {
        dim3 grid(6144 / 128, 16384 / 128);
        gemm_h<1><<<grid, 128, GEMM_SMEM_BYTES>>>(xh_ptr, wqh_ptr, nullptr, 16384, 6144, 2048);
    }
    // 2) Attention (register-resident flash, Tq=64, 2 CTA/SM)
    {
        dim3 grid(8, 16, 32);
        attn_mma<<<grid, 128, ATTN2_SMEM_BYTES>>>();
    }
    // 3) Output projection
    {
        dim3 grid(2048 / 128, 16384 / 128);
        gemm_h<0><<<grid, 128, GEMM_SMEM_BYTES>>>(yh_ptr, woh_ptr, out, 16384, 2048, 2048);
    }
}

// round 17
// speedup vs baseline: 1.0591x; 1.0591x over previous
#include <cuda_runtime.h>
#include <cuda_fp16.h>
#include <math.h>
#include <cstdint>

// Shapes: x[32,512,2048] f32, w_qkv[6144,2048], w_out[2048,2048], out[32,512,2048]

// Scratch (device globals: allocation-free per harness rules)
__device__ __half g_qh[32L * 16 * 512 * 128];   // [B,H,T,D] fp16, roped+scaled at gemm epilogue
__device__ __half g_kh[32L * 16 * 512 * 128];   // roped at gemm epilogue
__device__ __half g_vh[32L * 16 * 512 * 128];
__device__ __half g_yh[32L * 512 * 2048];       // [B,T,C] attn out fp16
__device__ __half g_xh[32L * 512 * 2048];       // x fp16
__device__ __half g_wqh[6144L * 2048];          // w_qkv fp16
__device__ __half g_woh[2048L * 2048];          // w_out fp16
__device__ float  g_cos[512 * 32];
__device__ float  g_sin[512 * 32];

// ===========================================================================
// Helpers
// ===========================================================================
__device__ __forceinline__ uint32_t smem_u32(const void* p) {
    uint32_t a;
    asm("{ .reg .u64 t; cvta.to.shared.u64 t, %1; cvt.u32.u64 %0, t; }" : "=r"(a) : "l"(p));
    return a;
}
__device__ __forceinline__ uint32_t swz(uint32_t off) { return off ^ ((off >> 3) & 0x70); }

#define CP_ASYNC16(dst, src) \
    asm volatile("cp.async.cg.shared.global [%0], [%1], 16;" :: "r"(dst), "l"(src))
#define CP_COMMIT() asm volatile("cp.async.commit_group;" ::: "memory")
#define CP_WAIT1() asm volatile("cp.async.wait_group 1;" ::: "memory")
#define CP_WAIT0() asm volatile("cp.async.wait_group 0;" ::: "memory")

#define MMA_F16(c, A0, A1, A2, A3, B0, B1) \
    asm volatile("mma.sync.aligned.m16n8k16.row.col.f32.f16.f16.f32 " \
        "{%0,%1,%2,%3},{%4,%5,%6,%7},{%8,%9},{%0,%1,%2,%3};" \
        : "+f"((c)[0]), "+f"((c)[1]), "+f"((c)[2]), "+f"((c)[3]) \
        : "r"(A0), "r"(A1), "r"(A2), "r"(A3), "r"(B0), "r"(B1))

#define LDMX4(r, addr) \
    asm volatile("ldmatrix.sync.aligned.m8n8.x4.shared.b16 {%0,%1,%2,%3}, [%4];" \
        : "=r"((r)[0]), "=r"((r)[1]), "=r"((r)[2]), "=r"((r)[3]) : "r"(addr))
#define LDMX4T(r, addr) \
    asm volatile("ldmatrix.sync.aligned.m8n8.x4.trans.shared.b16 {%0,%1,%2,%3}, [%4];" \
        : "=r"((r)[0]), "=r"((r)1 == 1 ? (r)[1] : (r)[1]), "=r"((r)[2]), "=r"((r)[3]) : "r"(addr))
#undef LDMX4T
#define LDMX4T(r, addr) \
    asm volatile("ldmatrix.sync.aligned.m8n8.x4.trans.shared.b16 {%0,%1,%2,%3}, [%4];" \
        : "=r"((r)[0]), "=r"((r)[1]), "=r"((r)[2]), "=r"((r)[3]) : "r"(addr))

__device__ __forceinline__ uint32_t pack2(float a, float b) {
    const __half2 h = __floats2half2_rn(a, b);
    return *(const uint32_t*)&h;
}

// ===========================================================================
// Merged prep: f32->f16 of x, w_qkv, w_out + rope tables. One launch.
// ===========================================================================
#define N4_X  8388608
#define N4_WQ 3145728
#define N4_WO 1048576
#define N4_TOTAL (N4_X + N4_WQ + N4_WO)

__global__ void prep_all(const float* __restrict__ x,
                         const float* __restrict__ wq,
                         const float* __restrict__ wo)
{
    const int i = blockIdx.x * blockDim.x + threadIdx.x;
    if (i < 512 * 32) {
        const int t = i >> 5, j = i & 31;
        const double freq = pow(10000.0, -(double)j / 32.0);
        const double ang = (double)t * freq;
        g_cos[i] = (float)cos(ang);
        g_sin[i] = (float)sin(ang);
    }
    if (i >= N4_TOTAL) return;
    const float* in;
    __half* out;
    int idx = i;
    if (idx < N4_X) { in = x; out = g_xh; }
    else if (idx < N4_X + N4_WQ) { idx -= N4_X; in = wq; out = g_wqh; }
    else { idx -= N4_X + N4_WQ; in = wo; out = g_woh; }
    const float4 v = ((const float4*)in)[idx];
    ((__half2*)out)[idx * 2]     = __floats2half2_rn(v.x, v.y);
    ((__half2*)out)[idx * 2 + 1] = __floats2half2_rn(v.z, v.w);
}

// ===========================================================================
// fp16 mma.sync GEMM (R15 config — best known): 128x128 CTA tile, BK=64,
// 4 warps (2x2) x 64x64 warp tile, 128 threads, 2-stage cp.async, 2 CTA/SM.
// MODE 0: fp32 row-major store.
// MODE 1: scatter q/k/v fp16 [B,H,T,D] with FUSED ROPE (+1/sqrt(D) q-scale):
//   thread holds rope pair (j, j+32) at (nf, nf+4) when wn==0 -> local rotate.
// ===========================================================================
#define GEMM_SMEM_BYTES 65536

template <int MODE>
__global__ void __launch_bounds__(128, 2) gemm_h(
    const __half* __restrict__ A, const __half* __restrict__ Bm,
    float* __restrict__ Cout, int M, int N, int K)
{
    extern __shared__ char smraw[];
    const uint32_t sb = smem_u32(smraw);
    const int tid = threadIdx.x;
    const int warp = tid >> 5, lane = tid & 31;
    const int wm = warp >> 1, wn = warp & 1;
    const int m0 = blockIdx.y * 128, n0 = blockIdx.x * 128;
    const int lrow = lane & 15, lcol = (lane >> 4) * 16;

    float acc[4][8][4];
#pragma unroll
    for (int i = 0; i < 4; i++)
#pragma unroll
        for (int j = 0; j < 8; j++)
#pragma unroll
            for (int q = 0; q < 4; q++) acc[i][j][q] = 0.f;

    const int nch = K / 64;

    auto load_chunk = [&](int c, int buf) {
        const int k0 = c * 64;
        const uint32_t abase = sb + buf * 32768;
        const uint32_t bbase = abase + 16384;
#pragma unroll
        for (int it = 0; it < 8; it++) {
            const int t = tid + it * 128;
            const int row = t >> 3, ch = t & 7;
            CP_ASYNC16(abase + swz((uint32_t)(row * 128 + ch * 16)),
                       A + (size_t)(m0 + row) * K + k0 + ch * 8);
        }
#pragma unroll
        for (int it = 0; it < 8; it++) {
            const int t = tid + it * 128;
            const int row = t >> 3, ch = t & 7;
            CP_ASYNC16(bbase + swz((uint32_t)(row * 128 + ch * 16)),
                       Bm + (size_t)(n0 + row) * K + k0 + ch * 8);
        }
    };

    load_chunk(0, 0);
    CP_COMMIT();

    for (int c = 0; c < nch; c++) {
        const int buf = c & 1;
        const bool has_next = (c + 1 < nch);
        if (has_next) {
            load_chunk(c + 1, (c + 1) & 1);
            CP_COMMIT();
            CP_WAIT1();
        } else {
            CP_WAIT0();
        }
        __syncthreads();

        const uint32_t abase = sb + buf * 32768;
        const uint32_t bbase = abase + 16384;

#pragma unroll
        for (int ks = 0; ks < 4; ks++) {
            uint32_t a[4][4], b[4][4];
#pragma unroll
            for (int mf = 0; mf < 4; mf++) {
                const int row = wm * 64 + mf * 16 + lrow;
                LDMX4(a[mf], abase + swz((uint32_t)(row * 128 + ks * 32 + lcol)));
            }
#pragma unroll
            for (int nb = 0; nb < 4; nb++) {
                const int row = wn * 64 + nb * 16 + lrow;
                LDMX4(b[nb], bbase + swz((uint32_t)(row * 128 + ks * 32 + lcol)));
            }
#pragma unroll
            for (int mf = 0; mf < 4; mf++)
#pragma unroll
                for (int nf = 0; nf < 8; nf++) {
                    const int nb = nf >> 1, i = nf & 1;
                    MMA_F16(acc[mf][nf], a[mf][0], a[mf][1], a[mf][2], a[mf][3],
                            b[nb][i], b[nb][i + 2]);
                }
        }
        __syncthreads();
    }

    const int g = lane >> 2, tig = lane & 3;
    if (MODE == 0) {
#pragma unroll
        for (int mf = 0; mf < 4; mf++) {
            const int mA = m0 + wm * 64 + mf * 16 + g;
#pragma unroll
            for (int nf = 0; nf < 8; nf++) {
                const int nn = n0 + wn * 64 + nf * 8 + tig * 2;
                *(float2*)(Cout + (size_t)mA * N + nn) =
                    make_float2(acc[mf][nf][0], acc[mf][nf][1]);
                *(float2*)(Cout + (size_t)(mA + 8) * N + nn) =
                    make_float2(acc[mf][nf][2], acc[mf][nf][3]);
            }
        }
    } else {
        const int which = n0 >> 11;      // 0=q, 1=k, 2=v (uniform per CTA)
        const int h = (n0 & 2047) >> 7;
        __half* basep = (which == 0) ? g_qh : (which == 1) ? g_kh : g_vh;
        const float scale = (which == 0) ? 0.08838834764831845f : 1.0f;

        if (which <= 1 && wn == 0) {
            // rope dims d = 0..63: rotate pairs (nf, nf+4) = (j, j+32), then scale
#pragma unroll
            for (int mf = 0; mf < 4; mf++) {
                const int mA = m0 + wm * 64 + mf * 16 + g;
                const int bA = mA >> 9, tA = mA & 511;
                const int mB = mA + 8;
                const int bB = mB >> 9, tB = mB & 511;
#pragma unroll
                for (int nf = 0; nf < 4; nf++) {
                    const int j0 = nf * 8 + tig * 2;
                    const float cA0 = g_cos[tA * 32 + j0], sA0 = g_sin[tA * 32 + j0];
                    const float cA1 = g_cos[tA * 32 + j0 + 1], sA1 = g_sin[tA * 32 + j0 + 1];
                    const float cB0 = g_cos[tB * 32 + j0], sB0 = g_sin[tB * 32 + j0];
                    const float cB1 = g_cos[tB * 32 + j0 + 1], sB1 = g_sin[tB * 32 + j0 + 1];
                    const float x1A0 = acc[mf][nf][0], x2A0 = acc[mf][nf + 4][0];
                    const float x1A1 = acc[mf][nf][1], x2A1 = acc[mf][nf + 4][1];
                    const float x1B0 = acc[mf][nf][2], x2B0 = acc[mf][nf + 4][2];
                    const float x1B1 = acc[mf][nf][3], x2B1 = acc[mf][nf + 4][3];
                    const size_t iA = ((size_t)(bA * 16 + h) * 512 + tA) * 128 + j0;
                    const size_t iB = ((size_t)(bB * 16 + h) * 512 + tB) * 128 + j0;
                    *(__half2*)&basep[iA] = __floats2half2_rn(
                        (x1A0 * cA0 - x2A0 * sA0) * scale, (x1A1 * cA1 - x2A1 * sA1) * scale);
                    *(__half2*)&basep[iA + 32] = __floats2half2_rn(
                        (x2A0 * cA0 + x1A0 * sA0) * scale, (x2A1 * cA1 + x1A1 * sA1) * scale);
                    *(__half2*)&basep[iB] = __floats2half2_rn(
                        (x1B0 * cB0 - x2B0 * sB0) * scale, (x1B1 * cB1 - x2B1 * sB1) * scale);
                    *(__half2*)&basep[iB + 32] = __floats2half2_rn(
                        (x2B0 * cB0 + x1B0 * sB0) * scale, (x2B1 * cB1 + x1B1 * sB1) * scale);
                }
            }
        } else {
#pragma unroll
            for (int mf = 0; mf < 4; mf++) {
                const int mA = m0 + wm * 64 + mf * 16 + g;
                const int bA = mA >> 9, tA = mA & 511;
                const int mB = mA + 8;
                const int bB = mB >> 9, tB = mB & 511;
#pragma unroll
                for (int nf = 0; nf < 8; nf++) {
                    const int d = wn * 64 + nf * 8 + tig * 2;
                    const size_t iA = ((size_t)(bA * 16 + h) * 512 + tA) * 128 + d;
                    const size_t iB = ((size_t)(bB * 16 + h) * 512 + tB) * 128 + d;
                    *(__half2*)&basep[iA] = __floats2half2_rn(
                        acc[mf][nf][0] * scale, acc[mf][nf][1] * scale);
                    *(__half2*)&basep[iB] = __floats2half2_rn(
                        acc[mf][nf][2] * scale, acc[mf][nf][3] * scale);
                }
            }
        }
    }
}

// ===========================================================================
// Register-resident fp16 flash attention (R14 config — best known).
// Tq=64, 4 warps (16 q-rows each), full 64 keys x 128 d per warp.
// P in registers; warp-local softmax. Double-buffered K/V. 2 CTA/SM.
// ===========================================================================
#define ASQ   0                        // 64 x 272B
#define ASK(b) (17408 + (b) * 17408)   // 2 x 64x272B
#define ASV(b) (52224 + (b) * 17408)   // 2 x 64x272B
#define ATTN2_SMEM_BYTES 87040

__global__ void __launch_bounds__(128, 2) attn_mma()
{
    extern __shared__ char smc[];
    const uint32_t sb = smem_u32(smc);
    const int tid = threadIdx.x;
    const int warp = tid >> 5, lane = tid & 31;
    const int g = lane >> 2, tig = lane & 3;
    const int lrow = lane & 15, lcol = (lane >> 4) * 16;
    const int qt = blockIdx.x, hh = blockIdx.y, bb = blockIdx.z;
    const int bh = bb * 16 + hh, q0 = qt * 64;
    const int arow = warp * 16;

    const __half* qbase = g_qh + (size_t)bh * 512 * 128;
    const __half* kbase = g_kh + (size_t)bh * 512 * 128;
    const __half* vbase = g_vh + (size_t)bh * 512 * 128;

    auto stage = [&](uint32_t dstB, const __half* src) {
#pragma unroll
        for (int it = 0; it < 8; it++) {
            const int p = tid + it * 128;
            const int row = p >> 4, ch = p & 15;
            CP_ASYNC16(sb + dstB + row * 272 + ch * 16,
                       src + row * 128 + ch * 8);
        }
    };

    const int nkt = qt + 1;
    stage(ASQ, qbase + (size_t)q0 * 128);
    stage(ASK(0), kbase);
    stage(ASV(0), vbase);
    CP_COMMIT();
    if (nkt > 1) {
        stage(ASK(1), kbase + 64 * 128);
        stage(ASV(1), vbase + 64 * 128);
        CP_COMMIT();
    }

    float o[16][4];
#pragma unroll
    for (int i = 0; i < 16; i++)
#pragma unroll
        for (int q = 0; q < 4; q++) o[i][q] = 0.f;
    float mA = -1e30f, mB = -1e30f, lA = 0.f, lB = 0.f;

    for (int kt = 0; kt < nkt; kt++) {
        const int buf = kt & 1;
        if (kt < nkt - 1) { CP_WAIT1(); } else { CP_WAIT0(); }
        __syncthreads();

        float sacc[8][4];
#pragma unroll
        for (int nf = 0; nf < 8; nf++)
#pragma unroll
            for (int q = 0; q < 4; q++) sacc[nf][q] = 0.f;

#pragma unroll
        for (int dc = 0; dc < 8; dc++) {
            uint32_t a[4];
            LDMX4(a, sb + ASQ + (uint32_t)((arow + lrow) * 272 + dc * 32 + lcol));
#pragma unroll
            for (int nb = 0; nb < 4; nb++) {
                uint32_t bf[4];
                LDMX4(bf, sb + ASK(buf) +
                      (uint32_t)((nb * 16 + lrow) * 272 + dc * 32 + lcol));
#pragma unroll
                for (int i = 0; i < 2; i++)
                    MMA_F16(sacc[nb * 2 + i], a[0], a[1], a[2], a[3],
                            bf[i], bf[i + 2]);
            }
        }

        if (kt == qt) {
            const int lrA = arow + g, lrB = lrA + 8;
#pragma unroll
            for (int nf = 0; nf < 8; nf++) {
                const int lc = nf * 8 + 2 * tig;
                if (lc > lrA)     sacc[nf][0] = -1e30f;
                if (lc + 1 > lrA) sacc[nf][1] = -1e30f;
                if (lc > lrB)     sacc[nf][2] = -1e30f;
                if (lc + 1 > lrB) sacc[nf][3] = -1e30f;
            }
        }

        float mAn = -1e30f, mBn = -1e30f;
#pragma unroll
        for (int nf = 0; nf < 8; nf++) {
            mAn = fmaxf(mAn, fmaxf(sacc[nf][0], sacc[nf][1]));
            mBn = fmaxf(mBn, fmaxf(sacc[nf][2], sacc[nf][3]));
        }
        mAn = fmaxf(mAn, __shfl_xor_sync(0xffffffffu, mAn, 1));
        mAn = fmaxf(mAn, __shfl_xor_sync(0xffffffffu, mAn, 2));
        mBn = fmaxf(mBn, __shfl_xor_sync(0xffffffffu, mBn, 1));
        mBn = fmaxf(mBn, __shfl_xor_sync(0xffffffffu, mBn, 2));
        const float mAnew = fmaxf(mA, mAn), mBnew = fmaxf(mB, mBn);
        const float alA = __expf(mA - mAnew), alB = __expf(mB - mBnew);
        mA = mAnew; mB = mBnew;

        uint32_t pf[4][4];
        float sA = 0.f, sB = 0.f;
#pragma unroll
        for (int kc = 0; kc < 4; kc++) {
            const float p0 = __expf(sacc[2 * kc][0] - mA);
            const float p1 = __expf(sacc[2 * kc][1] - mA);
            const float p2 = __expf(sacc[2 * kc][2] - mB);
            const float p3 = __expf(sacc[2 * kc][3] - mB);
            const float p4 = __expf(sacc[2 * kc + 1][0] - mA);
            const float p5 = __expf(sacc[2 * kc + 1][1] - mA);
            const float p6 = __expf(sacc[2 * kc + 1][2] - mB);
            const float p7 = __expf(sacc[2 * kc + 1][3] - mB);
            sA += p0 + p1 + p4 + p5;
            sB += p2 + p3 + p6 + p7;
            pf[kc][0] = pack2(p0, p1);
            pf[kc][1] = pack2(p2, p3);
            pf[kc][2] = pack2(p4, p5);
            pf[kc][3] = pack2(p6, p7);
        }
        sA += __shfl_xor_sync(0xffffffffu, sA, 1);
        sA += __shfl_xor_sync(0xffffffffu, sA, 2);
        sB += __shfl_xor_sync(0xffffffffu, sB, 1);
        sB += __shfl_xor_sync(0xffffffffu, sB, 2);
        lA = lA * alA + sA;
        lB = lB * alB + sB;

#pragma unroll
        for (int i = 0; i < 16; i++) {
            o[i][0] *= alA; o[i][1] *= alA;
            o[i][2] *= alB; o[i][3] *= alB;
        }

#pragma unroll
        for (int kc = 0; kc < 4; kc++) {
#pragma unroll
            for (int dblk = 0; dblk < 8; dblk++) {
                uint32_t bf[4];
                LDMX4T(bf, sb + ASV(buf) +
                       (uint32_t)((kc * 16 + lrow) * 272 + dblk * 32 + lcol));
                MMA_F16(o[dblk * 2],     pf[kc][0], pf[kc][1], pf[kc][2], pf[kc][3],
                        bf[0], bf[1]);
                MMA_F16(o[dblk * 2 + 1], pf[kc][0], pf[kc][1], pf[kc][2], pf[kc][3],
                        bf[2], bf[3]);
            }
        }
        __syncthreads();

        if (kt + 2 < nkt) {
            const int knext = (kt + 2) * 64;
            stage(ASK(buf), kbase + (size_t)knext * 128);
            stage(ASV(buf), vbase + (size_t)knext * 128);
            CP_COMMIT();
        }
    }

    const float invA = 1.f / lA, invB = 1.f / lB;
    const int tA = q0 + arow + g, tB = tA + 8;
#pragma unroll
    for (int nf2 = 0; nf2 < 16; nf2++) {
        const int d = nf2 * 8 + 2 * tig;
        *(__half2*)&g_yh[((size_t)bb * 512 + tA) * 2048 + hh * 128 + d] =
            __floats2half2_rn(o[nf2][0] * invA, o[nf2][1] * invA);
        *(__half2*)&g_yh[((size_t)bb * 512 + tB) * 2048 + hh * 128 + d] =
            __floats2half2_rn(o[nf2][2] * invB, o[nf2][3] * invB);
    }
}

// ---------------------------------------------------------------------------
extern "C" void kernel_launch(void* const* d_in, const int* in_sizes, int n_in,
                              void* d_out, int out_size)
{
    (void)in_sizes; (void)n_in; (void)out_size;
    const float* x     = (const float*)d_in[0];
    const float* w_qkv = (const float*)d_in[1];
    const float* w_out = (const float*)d_in[2];
    float* out = (float*)d_out;

    __half *xh_ptr, *wqh_ptr, *woh_ptr, *yh_ptr;
    cudaGetSymbolAddress((void**)&xh_ptr,  g_xh);
    cudaGetSymbolAddress((void**)&wqh_ptr, g_wqh);
    cudaGetSymbolAddress((void**)&woh_ptr, g_woh);
    cudaGetSymbolAddress((void**)&yh_ptr,  g_yh);

    cudaFuncSetAttribute(gemm_h<1>, cudaFuncAttributeMaxDynamicSharedMemorySize, GEMM_SMEM_BYTES);
    cudaFuncSetAttribute(gemm_h<0>, cudaFuncAttributeMaxDynamicSharedMemorySize, GEMM_SMEM_BYTES);
    cudaFuncSetAttribute(attn_mma, cudaFuncAttributeMaxDynamicSharedMemorySize, ATTN2_SMEM_BYTES);

    // 0) merged prep (fp16 converts + rope tables; tables needed by gemm1 epilogue)
    prep_all<<<(N4_TOTAL + 255) / 256, 256>>>(x, w_qkv, w_out);

    // 1) QKV projection with fused rope (+q scale) in epilogue
    {
        dim3 grid(6144 / 128, 16384 / 128);
        gemm_h<1><<<grid, 128, GEMM_SMEM_BYTES>>>(xh_ptr, wqh_ptr, nullptr, 16384, 6144, 2048);
    }
    // 2) Attention (register-resident flash, Tq=64, 2 CTA/SM)
    {
        dim3 grid(8, 16, 32);
        attn_mma<<<grid, 128, ATTN2_SMEM_BYTES>>>();
    }
    // 3) Output projection
    {
        dim3 grid(2048 / 128, 16384 / 128);
        gemm_h<0><<<grid, 128, GEMM_SMEM_BYTES>>>(yh_ptr, woh_ptr, out, 16384, 2048, 2048);
    }
}